// round 13
// baseline (speedup 1.0000x reference)
#include <cuda_runtime.h>
#include <cuda_fp16.h>

#define N_NODES 40000
#define N_EDGES 640000
#define IN_F    128
#define OUT_F   64
#define NK      8
#define FD      8

#define SCAN_BLK   256
#define N_PART     ((N_NODES + SCAN_BLK - 1) / SCAN_BLK)   // 157

// ---------------- persistent device scratch (no allocations allowed) ----------------
// ZERO INVARIANT: g_deg, g_scanstate, g_blkcounter are zero at entry of every
// kernel_launch call (statically zero-initialized; each call restores them:
// scan_onepass re-zeros g_deg, scatter re-zeros scanstate+counter).
__device__ int          g_deg[N_NODES];
__device__ int          g_rowptr[N_NODES + 1];
__device__ int          g_cursor[N_NODES];
__device__ int          g_csrdst[N_EDGES];
__device__ unsigned int g_blkcounter;
__device__ unsigned int g_scanstate[N_PART];     // packed: flag<<30 | value
__device__ float        g_hn[N_NODES * OUT_F];   // h_normed fp32 (residual + h_dst iter0)
__device__ __half       g_hnh[N_NODES * OUT_F];  // h_normed fp16 (per-edge gather table)
__device__ float        g_b0[N_NODES * OUT_F];   // h_dst ping
__device__ float        g_b1[N_NODES * OUT_F];   // h_dst pong

// block-level exclusive scan helper: returns exclusive prefix of v within the
// block; *total gets the block sum. 256 threads = 8 warps.
__device__ __forceinline__ int block_excl_scan(int v, int* total) {
    __shared__ int wsum[8];
    int lane = threadIdx.x & 31, wid = threadIdx.x >> 5;
    int incl = v;
    #pragma unroll
    for (int off = 1; off < 32; off <<= 1) {
        int u = __shfl_up_sync(0xffffffffu, incl, off);
        if (lane >= off) incl += u;
    }
    if (lane == 31) wsum[wid] = incl;
    __syncthreads();
    if (wid == 0) {
        int wi = (lane < 8) ? wsum[lane] : 0;
        #pragma unroll
        for (int off = 1; off < 8; off <<= 1) {
            int u = __shfl_up_sync(0xffffffffu, wi, off);
            if (lane >= off) wi += u;
        }
        if (lane < 8) wsum[lane] = wi;   // inclusive warp sums
    }
    __syncthreads();
    int warpoff = (wid > 0) ? wsum[wid - 1] : 0;
    *total = wsum[7];
    return warpoff + (incl - v);
}

// single-pass scan with decoupled lookback (ticket ordering; all 157 blocks co-resident).
// Consumes g_deg and RE-ZEROS it (restores the zero invariant for the next call).
__global__ void scan_onepass_kernel() {
    __shared__ int sbid;
    __shared__ int sexcl;
    if (threadIdx.x == 0) sbid = (int)atomicAdd(&g_blkcounter, 1u);
    __syncthreads();
    int bid = sbid;
    int i = bid * SCAN_BLK + threadIdx.x;
    int v = (i < N_NODES) ? g_deg[i] : 0;
    int total;
    int ex = block_excl_scan(v, &total);

    if (threadIdx.x == 0) {
        int excl = 0;
        if (bid == 0) {
            atomicExch(&g_scanstate[0], (2u << 30) | (unsigned)total);
        } else {
            atomicExch(&g_scanstate[bid], (1u << 30) | (unsigned)total);
            int p = bid - 1;
            while (p >= 0) {
                unsigned st;
                do { st = atomicAdd(&g_scanstate[p], 0u); } while ((st >> 30) == 0u);
                excl += (int)(st & 0x3FFFFFFFu);
                if ((st >> 30) == 2u) break;
                p--;
            }
            atomicExch(&g_scanstate[bid], (2u << 30) | (unsigned)(excl + total));
        }
        sexcl = excl;
        if (bid == N_PART - 1) g_rowptr[N_NODES] = excl + total;   // = N_EDGES
    }
    __syncthreads();
    if (i < N_NODES) {
        int val = sexcl + ex;
        g_rowptr[i] = val;
        g_cursor[i] = val;
        g_deg[i] = 0;                      // restore zero invariant
    }
}

// 1 edge per thread. Also resets scan state + ticket counter for the next call
// (ordered before the next replay's scan by stream order).
__global__ void scatter_kernel(const int* __restrict__ src, const int* __restrict__ dst) {
    int e = blockIdx.x * blockDim.x + threadIdx.x;
    if (blockIdx.x == 0) {
        if (threadIdx.x < N_PART) g_scanstate[threadIdx.x] = 0u;
        if (threadIdx.x == N_PART) g_blkcounter = 0u;
    }
    if (e < N_EDGES) {
        int s   = src[e];
        int pos = atomicAdd(&g_cursor[s], 1);
        g_csrdst[pos] = dst[e];
    }
}

// ---------------- fused GEMM + bias + leaky_relu + l2norm + EDGE HISTOGRAM ----------------
// 625 blocks x 256 threads = 160000 threads; each histograms 4 edges (int4 load +
// 4 fire-and-forget REDs) -- overlaps the atomic latency with the FMA mainloop.
// g_deg is zero at entry per the zero invariant.
__global__ __launch_bounds__(256) void gemm_norm_kernel(
        const float* __restrict__ x, const float* __restrict__ w,
        const float* __restrict__ bias, const int* __restrict__ src) {
    __shared__ float xs[64][65];   // x chunk 64 rows x 64 k (padded); reused as out tile
    __shared__ float ws[64][64];   // w chunk 64 k x 64 cols

    int t    = threadIdx.x;
    int row0 = blockIdx.x * 64;
    int tx   = t & 15;     // col group (4 cols)
    int ty   = t >> 4;     // row group (4 rows)

    // fused histogram: 4 edges per thread (covers N_EDGES exactly)
    {
        int q = blockIdx.x * 256 + t;           // 0..159999
        int4 s4 = __ldg(reinterpret_cast<const int4*>(src) + q);
        atomicAdd(&g_deg[s4.x], 1);
        atomicAdd(&g_deg[s4.y], 1);
        atomicAdd(&g_deg[s4.z], 1);
        atomicAdd(&g_deg[s4.w], 1);
    }

    float acc[4][4];
    #pragma unroll
    for (int i = 0; i < 4; i++)
        #pragma unroll
        for (int j = 0; j < 4; j++) acc[i][j] = 0.0f;

    for (int kc = 0; kc < IN_F; kc += 64) {
        #pragma unroll
        for (int i = 0; i < 4; i++) {
            int li = t + i * 256;           // 0..1023
            int r  = li >> 4;               // 0..63
            int c4 = li & 15;               // 0..15
            float4 v = *reinterpret_cast<const float4*>(x + (size_t)(row0 + r) * IN_F + kc + c4 * 4);
            xs[r][c4 * 4 + 0] = v.x; xs[r][c4 * 4 + 1] = v.y;
            xs[r][c4 * 4 + 2] = v.z; xs[r][c4 * 4 + 3] = v.w;
        }
        #pragma unroll
        for (int i = 0; i < 4; i++) {
            int li = t + i * 256;
            int r  = li >> 4;
            int c4 = li & 15;
            float4 v = *reinterpret_cast<const float4*>(w + (size_t)(kc + r) * OUT_F + c4 * 4);
            *reinterpret_cast<float4*>(&ws[r][c4 * 4]) = v;
        }
        __syncthreads();

        #pragma unroll
        for (int k = 0; k < 64; k++) {
            float4 b = *reinterpret_cast<const float4*>(&ws[k][tx * 4]);
            float a0 = xs[ty * 4 + 0][k];
            float a1 = xs[ty * 4 + 1][k];
            float a2 = xs[ty * 4 + 2][k];
            float a3 = xs[ty * 4 + 3][k];
            acc[0][0] += a0 * b.x; acc[0][1] += a0 * b.y; acc[0][2] += a0 * b.z; acc[0][3] += a0 * b.w;
            acc[1][0] += a1 * b.x; acc[1][1] += a1 * b.y; acc[1][2] += a1 * b.z; acc[1][3] += a1 * b.w;
            acc[2][0] += a2 * b.x; acc[2][1] += a2 * b.y; acc[2][2] += a2 * b.z; acc[2][3] += a2 * b.w;
            acc[3][0] += a3 * b.x; acc[3][1] += a3 * b.y; acc[3][2] += a3 * b.z; acc[3][3] += a3 * b.w;
        }
        __syncthreads();
    }

    // bias + leaky_relu into out tile (reuse xs)
    float4 bv = *reinterpret_cast<const float4*>(bias + tx * 4);
    float bb[4] = {bv.x, bv.y, bv.z, bv.w};
    #pragma unroll
    for (int i = 0; i < 4; i++)
        #pragma unroll
        for (int j = 0; j < 4; j++) {
            float v = acc[i][j] + bb[j];
            v = (v > 0.0f) ? v : 0.01f * v;
            xs[ty * 4 + i][tx * 4 + j] = v;
        }
    __syncthreads();

    // per-factor l2norm -> fp32 table (residual) + fp16 table (gathers)
    for (int p = t; p < 512; p += 256) {
        int r  = p >> 3;
        int kk = p & 7;
        float vreg[8];
        float ss = 0.0f;
        #pragma unroll
        for (int i = 0; i < 8; i++) {
            vreg[i] = xs[r][kk * 8 + i];
            ss += vreg[i] * vreg[i];
        }
        float rs = rsqrtf(ss);
        size_t off = (size_t)(row0 + r) * OUT_F + kk * 8;
        union { __half h[8]; uint4 u; } pk;
        #pragma unroll
        for (int i = 0; i < 8; i++) {
            float o = vreg[i] * rs;
            g_hn[off + i] = o;
            pk.h[i] = __float2half_rn(o);
        }
        *reinterpret_cast<uint4*>(g_hnh + off) = pk.u;
    }
}

// ---------------- one disentangle iteration (fused softmax + aggregate + residual + norm) ----
// Warp = one node. Lane = (factor k = lane&7, edge-slot j = lane>>3).
// All <=32 edge indices of the node loaded by ONE warp-wide coalesced LDG
// (csrdst[e0+lane]) and distributed via shfl -- feature-gather addresses do not
// depend on an in-flight memory load, so a 1-deep pipeline (prefetch qn while
// consuming q) fully overlaps L2 latency. Inactive trips masked branchlessly.
// Butterfly shfl_xor (8,16) sums the 4 edge-slots; lanes 0..7 finish.
__global__ __launch_bounds__(256, 6) void attn_kernel(int iter, float* __restrict__ out_final) {
    int n = (blockIdx.x * blockDim.x + threadIdx.x) >> 5;
    if (n >= N_NODES) return;
    int lane = threadIdx.x & 31;
    int k = lane & 7;
    int j = lane >> 3;       // 0..3

    const float* hin  = (iter == 0) ? g_hn : ((iter == 1) ? g_b0 : g_b1);
    float*       hout = (iter == 0) ? g_b0 : ((iter == 1) ? g_b1 : out_final);

    const float4* hdr = reinterpret_cast<const float4*>(hin + (size_t)n * OUT_F + k * FD);
    float4 h0 = __ldg(hdr + 0);
    float4 h1 = __ldg(hdr + 1);

    float nu0 = 0.f, nu1 = 0.f, nu2 = 0.f, nu3 = 0.f;
    float nu4 = 0.f, nu5 = 0.f, nu6 = 0.f, nu7 = 0.f;
    float den = 0.f;

    int e0 = __ldg(&g_rowptr[n]);
    int e1 = __ldg(&g_rowptr[n + 1]);
    int deg = e1 - e0;

    for (int base = 0; base < deg; base += 32) {
        int cnt = deg - base; if (cnt > 32) cnt = 32;
        // one coalesced warp-wide index load covers this whole chunk
        int myidx = (base + lane < deg) ? __ldg(&g_csrdst[e0 + base + lane]) : 0;

        int maxtrips = (cnt + 3) >> 2;
        int t = j;
        int d = __shfl_sync(0xffffffffu, myidx, t & 31);
        uint4 q = __ldg(reinterpret_cast<const uint4*>(g_hnh + (size_t)d * OUT_F + k * FD));

        for (int tr = 0; tr < maxtrips; tr++) {
            int t2 = t + 4;
            // prefetch next trip's features (address from registers only)
            int d2 = __shfl_sync(0xffffffffu, myidx, t2 & 31);
            uint4 qn = __ldg(reinterpret_cast<const uint4*>(g_hnh + (size_t)d2 * OUT_F + k * FD));

            float2 fa = __half22float2(*reinterpret_cast<const __half2*>(&q.x));
            float2 fb = __half22float2(*reinterpret_cast<const __half2*>(&q.y));
            float2 fc = __half22float2(*reinterpret_cast<const __half2*>(&q.z));
            float2 fd = __half22float2(*reinterpret_cast<const __half2*>(&q.w));
            float s = h0.x * fa.x + h0.y * fa.y + h0.z * fb.x + h0.w * fb.y
                    + h1.x * fc.x + h1.y * fc.y + h1.z * fd.x + h1.w * fd.y;
            float ex = (t < cnt) ? __expf(s) : 0.0f;   // branchless mask for ragged tail
            den += ex;
            nu0 += ex * fa.x; nu1 += ex * fa.y; nu2 += ex * fb.x; nu3 += ex * fb.y;
            nu4 += ex * fc.x; nu5 += ex * fc.y; nu6 += ex * fd.x; nu7 += ex * fd.y;

            q = qn; t = t2;
        }
    }

    // butterfly reduce across the 4 edge-slots (lanes k, k+8, k+16, k+24)
    #pragma unroll
    for (int m = 8; m <= 16; m <<= 1) {
        den += __shfl_xor_sync(0xffffffffu, den, m);
        nu0 += __shfl_xor_sync(0xffffffffu, nu0, m);
        nu1 += __shfl_xor_sync(0xffffffffu, nu1, m);
        nu2 += __shfl_xor_sync(0xffffffffu, nu2, m);
        nu3 += __shfl_xor_sync(0xffffffffu, nu3, m);
        nu4 += __shfl_xor_sync(0xffffffffu, nu4, m);
        nu5 += __shfl_xor_sync(0xffffffffu, nu5, m);
        nu6 += __shfl_xor_sync(0xffffffffu, nu6, m);
        nu7 += __shfl_xor_sync(0xffffffffu, nu7, m);
    }

    if (lane < 8) {
        float inv = (deg > 0) ? (1.0f / den) : 0.0f;

        const float4* hnr = reinterpret_cast<const float4*>(g_hn + (size_t)n * OUT_F + k * FD);
        float4 a0 = __ldg(hnr + 0);
        float4 a1 = __ldg(hnr + 1);

        float o0 = nu0 * inv + a0.x;
        float o1 = nu1 * inv + a0.y;
        float o2 = nu2 * inv + a0.z;
        float o3 = nu3 * inv + a0.w;
        float o4 = nu4 * inv + a1.x;
        float o5 = nu5 * inv + a1.y;
        float o6 = nu6 * inv + a1.z;
        float o7 = nu7 * inv + a1.w;

        float ss = o0*o0 + o1*o1 + o2*o2 + o3*o3 + o4*o4 + o5*o5 + o6*o6 + o7*o7;
        float r  = rsqrtf(ss);

        float4* op = reinterpret_cast<float4*>(hout + (size_t)n * OUT_F + k * FD);
        op[0] = make_float4(o0 * r, o1 * r, o2 * r, o3 * r);
        op[1] = make_float4(o4 * r, o5 * r, o6 * r, o7 * r);
    }
}

// ---------------- launch ----------------
extern "C" void kernel_launch(void* const* d_in, const int* in_sizes, int n_in,
                              void* d_out, int out_size) {
    const float* x    = (const float*)d_in[0];   // [40000,128]
    const float* w    = (const float*)d_in[1];   // [128,64]
    const float* bias = (const float*)d_in[2];   // [64]
    const int*   ei   = (const int*)d_in[3];     // [2,640000]
    const int*   src  = ei;
    const int*   dst  = ei + N_EDGES;
    float*       out  = (float*)d_out;           // [40000,64]

    // GEMM + fused edge histogram (g_deg zero by invariant)
    gemm_norm_kernel<<<N_NODES / 64, 256>>>(x, w, bias, src);

    scan_onepass_kernel<<<N_PART, SCAN_BLK>>>();   // also re-zeros g_deg
    scatter_kernel<<<(N_EDGES + 255) / 256, 256>>>(src, dst);  // also resets scan state

    // one warp per node: 40000 warps -> 5000 blocks of 256 threads
    int attn_blocks = (N_NODES * 32 + 255) / 256;
    attn_kernel<<<attn_blocks, 256>>>(0, out);
    attn_kernel<<<attn_blocks, 256>>>(1, out);
    attn_kernel<<<attn_blocks, 256>>>(2, out);
}

// round 16
// speedup vs baseline: 1.1748x; 1.1748x over previous
#include <cuda_runtime.h>
#include <cuda_fp16.h>

#define N_NODES 40000
#define N_EDGES 640000
#define IN_F    128
#define OUT_F   64
#define NK      8
#define FD      8

#define SCAN_BLK   256
#define N_PART     ((N_NODES + SCAN_BLK - 1) / SCAN_BLK)   // 157

// ---------------- persistent device scratch (no allocations allowed) ----------------
// ZERO INVARIANT: g_deg, g_scanstate, g_blkcounter are zero at entry of every
// kernel_launch call (statically zero-initialized; each call restores them:
// scan_onepass re-zeros g_deg, scatter re-zeros scanstate+counter).
// ALIGNMENT BY CONSTRUCTION: every vector-accessed table is an array OF
// float4/uint4 -- 16B alignment guaranteed by the type system (R14/R15
// 'misaligned address' eradication; attributes proved unreliable).
__device__ int          g_deg[N_NODES];
__device__ int          g_rowptr[N_NODES + 1];
__device__ int          g_cursor[N_NODES];
__device__ int          g_csrdst[N_EDGES];
__device__ unsigned int g_blkcounter;
__device__ unsigned int g_scanstate[N_PART];        // packed: flag<<30 | value
__device__ float4       g_hn4 [N_NODES * 16];       // h_normed fp32: (n,k) -> [n*16+k*2, +1]
__device__ uint4        g_hnh4[N_NODES * 8];        // h_normed fp16: (n,k) -> n*8+k (8 halves)
__device__ float4       g_b0_4[N_NODES * 16];       // h_dst ping
__device__ float4       g_b1_4[N_NODES * 16];       // h_dst pong

// block-level exclusive scan helper: returns exclusive prefix of v within the
// block; *total gets the block sum. 256 threads = 8 warps.
__device__ __forceinline__ int block_excl_scan(int v, int* total) {
    __shared__ int wsum[8];
    int lane = threadIdx.x & 31, wid = threadIdx.x >> 5;
    int incl = v;
    #pragma unroll
    for (int off = 1; off < 32; off <<= 1) {
        int u = __shfl_up_sync(0xffffffffu, incl, off);
        if (lane >= off) incl += u;
    }
    if (lane == 31) wsum[wid] = incl;
    __syncthreads();
    if (wid == 0) {
        int wi = (lane < 8) ? wsum[lane] : 0;
        #pragma unroll
        for (int off = 1; off < 8; off <<= 1) {
            int u = __shfl_up_sync(0xffffffffu, wi, off);
            if (lane >= off) wi += u;
        }
        if (lane < 8) wsum[lane] = wi;   // inclusive warp sums
    }
    __syncthreads();
    int warpoff = (wid > 0) ? wsum[wid - 1] : 0;
    *total = wsum[7];
    return warpoff + (incl - v);
}

// single-pass scan with decoupled lookback (ticket ordering; all 157 blocks co-resident).
// Consumes g_deg and RE-ZEROS it (restores the zero invariant for the next call).
__global__ void scan_onepass_kernel() {
    __shared__ int sbid;
    __shared__ int sexcl;
    if (threadIdx.x == 0) sbid = (int)atomicAdd(&g_blkcounter, 1u);
    __syncthreads();
    int bid = sbid;
    int i = bid * SCAN_BLK + threadIdx.x;
    int v = (i < N_NODES) ? g_deg[i] : 0;
    int total;
    int ex = block_excl_scan(v, &total);

    if (threadIdx.x == 0) {
        int excl = 0;
        if (bid == 0) {
            atomicExch(&g_scanstate[0], (2u << 30) | (unsigned)total);
        } else {
            atomicExch(&g_scanstate[bid], (1u << 30) | (unsigned)total);
            int p = bid - 1;
            while (p >= 0) {
                unsigned st;
                do { st = atomicAdd(&g_scanstate[p], 0u); } while ((st >> 30) == 0u);
                excl += (int)(st & 0x3FFFFFFFu);
                if ((st >> 30) == 2u) break;
                p--;
            }
            atomicExch(&g_scanstate[bid], (2u << 30) | (unsigned)(excl + total));
        }
        sexcl = excl;
        if (bid == N_PART - 1) g_rowptr[N_NODES] = excl + total;   // = N_EDGES
    }
    __syncthreads();
    if (i < N_NODES) {
        int val = sexcl + ex;
        g_rowptr[i] = val;
        g_cursor[i] = val;
        g_deg[i] = 0;                      // restore zero invariant
    }
}

// 1 edge per thread. Also resets scan state + ticket counter for the next call
// (ordered before the next replay's scan by stream order).
__global__ void scatter_kernel(const int* __restrict__ src, const int* __restrict__ dst) {
    int e = blockIdx.x * blockDim.x + threadIdx.x;
    if (blockIdx.x == 0) {
        if (threadIdx.x < N_PART) g_scanstate[threadIdx.x] = 0u;
        if (threadIdx.x == N_PART) g_blkcounter = 0u;
    }
    if (e < N_EDGES) {
        int s   = src[e];
        int pos = atomicAdd(&g_cursor[s], 1);
        g_csrdst[pos] = dst[e];
    }
}

// ---------------- fused GEMM + bias + leaky_relu + l2norm + EDGE HISTOGRAM ----------------
// 625 blocks x 256 threads = 160000 threads; each histograms 4 edges (int4 load +
// 4 fire-and-forget REDs) -- overlaps the atomic latency with the FMA mainloop.
// g_deg is zero at entry per the zero invariant.
__global__ __launch_bounds__(256) void gemm_norm_kernel(
        const float* __restrict__ x, const float* __restrict__ w,
        const float* __restrict__ bias, const int* __restrict__ src) {
    __shared__ float xs[64][65];   // x chunk 64 rows x 64 k (padded); reused as out tile
    __shared__ float ws[64][64];   // w chunk 64 k x 64 cols

    int t    = threadIdx.x;
    int row0 = blockIdx.x * 64;
    int tx   = t & 15;     // col group (4 cols)
    int ty   = t >> 4;     // row group (4 rows)

    // fused histogram: 4 edges per thread (covers N_EDGES exactly)
    {
        int q = blockIdx.x * 256 + t;           // 0..159999
        int4 s4 = __ldg(reinterpret_cast<const int4*>(src) + q);
        atomicAdd(&g_deg[s4.x], 1);
        atomicAdd(&g_deg[s4.y], 1);
        atomicAdd(&g_deg[s4.z], 1);
        atomicAdd(&g_deg[s4.w], 1);
    }

    float acc[4][4];
    #pragma unroll
    for (int i = 0; i < 4; i++)
        #pragma unroll
        for (int j = 0; j < 4; j++) acc[i][j] = 0.0f;

    for (int kc = 0; kc < IN_F; kc += 64) {
        #pragma unroll
        for (int i = 0; i < 4; i++) {
            int li = t + i * 256;           // 0..1023
            int r  = li >> 4;               // 0..63
            int c4 = li & 15;               // 0..15
            float4 v = *reinterpret_cast<const float4*>(x + (size_t)(row0 + r) * IN_F + kc + c4 * 4);
            xs[r][c4 * 4 + 0] = v.x; xs[r][c4 * 4 + 1] = v.y;
            xs[r][c4 * 4 + 2] = v.z; xs[r][c4 * 4 + 3] = v.w;
        }
        #pragma unroll
        for (int i = 0; i < 4; i++) {
            int li = t + i * 256;
            int r  = li >> 4;
            int c4 = li & 15;
            float4 v = *reinterpret_cast<const float4*>(w + (size_t)(kc + r) * OUT_F + c4 * 4);
            ws[r][c4 * 4 + 0] = v.x; ws[r][c4 * 4 + 1] = v.y;
            ws[r][c4 * 4 + 2] = v.z; ws[r][c4 * 4 + 3] = v.w;
        }
        __syncthreads();

        #pragma unroll
        for (int k = 0; k < 64; k++) {
            float b0 = ws[k][tx * 4 + 0];
            float b1 = ws[k][tx * 4 + 1];
            float b2 = ws[k][tx * 4 + 2];
            float b3 = ws[k][tx * 4 + 3];
            float a0 = xs[ty * 4 + 0][k];
            float a1 = xs[ty * 4 + 1][k];
            float a2 = xs[ty * 4 + 2][k];
            float a3 = xs[ty * 4 + 3][k];
            acc[0][0] += a0 * b0; acc[0][1] += a0 * b1; acc[0][2] += a0 * b2; acc[0][3] += a0 * b3;
            acc[1][0] += a1 * b0; acc[1][1] += a1 * b1; acc[1][2] += a1 * b2; acc[1][3] += a1 * b3;
            acc[2][0] += a2 * b0; acc[2][1] += a2 * b1; acc[2][2] += a2 * b2; acc[2][3] += a2 * b3;
            acc[3][0] += a3 * b0; acc[3][1] += a3 * b1; acc[3][2] += a3 * b2; acc[3][3] += a3 * b3;
        }
        __syncthreads();
    }

    // bias + leaky_relu into out tile (reuse xs)
    float bb0 = bias[tx * 4 + 0], bb1 = bias[tx * 4 + 1];
    float bb2 = bias[tx * 4 + 2], bb3 = bias[tx * 4 + 3];
    #pragma unroll
    for (int i = 0; i < 4; i++) {
        float v0 = acc[i][0] + bb0; v0 = (v0 > 0.0f) ? v0 : 0.01f * v0;
        float v1 = acc[i][1] + bb1; v1 = (v1 > 0.0f) ? v1 : 0.01f * v1;
        float v2 = acc[i][2] + bb2; v2 = (v2 > 0.0f) ? v2 : 0.01f * v2;
        float v3 = acc[i][3] + bb3; v3 = (v3 > 0.0f) ? v3 : 0.01f * v3;
        xs[ty * 4 + i][tx * 4 + 0] = v0;
        xs[ty * 4 + i][tx * 4 + 1] = v1;
        xs[ty * 4 + i][tx * 4 + 2] = v2;
        xs[ty * 4 + i][tx * 4 + 3] = v3;
    }
    __syncthreads();

    // per-factor l2norm -> fp32 table (residual) + fp16 table (gathers)
    for (int p = t; p < 512; p += 256) {
        int r  = p >> 3;
        int kk = p & 7;
        float vreg[8];
        float ss = 0.0f;
        #pragma unroll
        for (int i = 0; i < 8; i++) {
            vreg[i] = xs[r][kk * 8 + i];
            ss += vreg[i] * vreg[i];
        }
        float rs = rsqrtf(ss);
        float o[8];
        #pragma unroll
        for (int i = 0; i < 8; i++) o[i] = vreg[i] * rs;

        int n = row0 + r;
        g_hn4[n * 16 + kk * 2 + 0] = make_float4(o[0], o[1], o[2], o[3]);
        g_hn4[n * 16 + kk * 2 + 1] = make_float4(o[4], o[5], o[6], o[7]);

        union { __half h[8]; uint4 u; } pk;
        #pragma unroll
        for (int i = 0; i < 8; i++) pk.h[i] = __float2half_rn(o[i]);
        g_hnh4[n * 8 + kk] = pk.u;
    }
}

// helper: accumulate one fp16 feature row into the softmax sums
__device__ __forceinline__ void accum_edge(
    uint4 q, float4 h0, float4 h1, bool valid,
    float& den, float& nu0, float& nu1, float& nu2, float& nu3,
    float& nu4, float& nu5, float& nu6, float& nu7)
{
    float2 fa = __half22float2(*reinterpret_cast<const __half2*>(&q.x));
    float2 fb = __half22float2(*reinterpret_cast<const __half2*>(&q.y));
    float2 fc = __half22float2(*reinterpret_cast<const __half2*>(&q.z));
    float2 fd = __half22float2(*reinterpret_cast<const __half2*>(&q.w));
    float s = h0.x * fa.x + h0.y * fa.y + h0.z * fb.x + h0.w * fb.y
            + h1.x * fc.x + h1.y * fc.y + h1.z * fd.x + h1.w * fd.y;
    float ex = valid ? __expf(s) : 0.0f;
    den += ex;
    nu0 += ex * fa.x; nu1 += ex * fa.y; nu2 += ex * fb.x; nu3 += ex * fb.y;
    nu4 += ex * fc.x; nu5 += ex * fc.y; nu6 += ex * fd.x; nu7 += ex * fd.y;
}

// ---------------- one disentangle iteration (fused softmax + aggregate + residual + norm) ----
// Warp = one node. Lane = (factor k = lane&7, edge-slot j = lane>>3).
// 4 edges per trip (e, e+4, e+8, e+12; stride 16). Tail indices are CLAMPED to
// the last valid edge (never out of bounds, even under compiler speculation);
// their contributions are masked. All 4 idx loads issue together, then all 4
// gathers -- 4-deep MLP, one exposed chain per 16 edges (deg~16 -> 1 trip).
// No shfl in the loop (R13 lesson). Butterfly shfl_xor (8,16) reduces at end.
__global__ __launch_bounds__(256) void attn_kernel(int iter, float4* __restrict__ out_final) {
    int n = (blockIdx.x * blockDim.x + threadIdx.x) >> 5;
    if (n >= N_NODES) return;
    int lane = threadIdx.x & 31;
    int k = lane & 7;
    int j = lane >> 3;       // 0..3

    const float4* hin4  = (iter == 0) ? g_hn4 : ((iter == 1) ? g_b0_4 : g_b1_4);
    float4*       hout4 = (iter == 0) ? g_b0_4 : ((iter == 1) ? g_b1_4 : out_final);

    float4 h0 = __ldg(&hin4[n * 16 + k * 2 + 0]);
    float4 h1 = __ldg(&hin4[n * 16 + k * 2 + 1]);

    float nu0 = 0.f, nu1 = 0.f, nu2 = 0.f, nu3 = 0.f;
    float nu4 = 0.f, nu5 = 0.f, nu6 = 0.f, nu7 = 0.f;
    float den = 0.f;

    int e0 = __ldg(&g_rowptr[n]);
    int e1 = __ldg(&g_rowptr[n + 1]);

    for (int e = e0 + j; e < e1; e += 16) {
        int last = e1 - 1;
        int eb = e + 4, ec = e + 8, ed = e + 12;
        bool vb = eb < e1, vc = ec < e1, vd = ed < e1;
        int ib = vb ? eb : last;    // clamped: always in-bounds
        int ic = vc ? ec : last;
        int id = vd ? ed : last;
        // 4 independent index loads
        int da = __ldg(&g_csrdst[e]);
        int db = __ldg(&g_csrdst[ib]);
        int dc = __ldg(&g_csrdst[ic]);
        int dd = __ldg(&g_csrdst[id]);
        // 4 independent feature gathers (uint4-typed table: 16B aligned by type)
        uint4 qa = __ldg(&g_hnh4[(size_t)da * 8 + k]);
        uint4 qb = __ldg(&g_hnh4[(size_t)db * 8 + k]);
        uint4 qc = __ldg(&g_hnh4[(size_t)dc * 8 + k]);
        uint4 qd = __ldg(&g_hnh4[(size_t)dd * 8 + k]);

        accum_edge(qa, h0, h1, true, den, nu0, nu1, nu2, nu3, nu4, nu5, nu6, nu7);
        accum_edge(qb, h0, h1, vb,   den, nu0, nu1, nu2, nu3, nu4, nu5, nu6, nu7);
        accum_edge(qc, h0, h1, vc,   den, nu0, nu1, nu2, nu3, nu4, nu5, nu6, nu7);
        accum_edge(qd, h0, h1, vd,   den, nu0, nu1, nu2, nu3, nu4, nu5, nu6, nu7);
    }

    // butterfly reduce across the 4 edge-slots (lanes k, k+8, k+16, k+24)
    #pragma unroll
    for (int m = 8; m <= 16; m <<= 1) {
        den += __shfl_xor_sync(0xffffffffu, den, m);
        nu0 += __shfl_xor_sync(0xffffffffu, nu0, m);
        nu1 += __shfl_xor_sync(0xffffffffu, nu1, m);
        nu2 += __shfl_xor_sync(0xffffffffu, nu2, m);
        nu3 += __shfl_xor_sync(0xffffffffu, nu3, m);
        nu4 += __shfl_xor_sync(0xffffffffu, nu4, m);
        nu5 += __shfl_xor_sync(0xffffffffu, nu5, m);
        nu6 += __shfl_xor_sync(0xffffffffu, nu6, m);
        nu7 += __shfl_xor_sync(0xffffffffu, nu7, m);
    }

    if (lane < 8) {
        float inv = (e1 > e0) ? (1.0f / den) : 0.0f;

        float4 a0 = __ldg(&g_hn4[n * 16 + k * 2 + 0]);
        float4 a1 = __ldg(&g_hn4[n * 16 + k * 2 + 1]);

        float o0 = nu0 * inv + a0.x;
        float o1 = nu1 * inv + a0.y;
        float o2 = nu2 * inv + a0.z;
        float o3 = nu3 * inv + a0.w;
        float o4 = nu4 * inv + a1.x;
        float o5 = nu5 * inv + a1.y;
        float o6 = nu6 * inv + a1.z;
        float o7 = nu7 * inv + a1.w;

        float ss = o0*o0 + o1*o1 + o2*o2 + o3*o3 + o4*o4 + o5*o5 + o6*o6 + o7*o7;
        float r  = rsqrtf(ss);

        hout4[n * 16 + k * 2 + 0] = make_float4(o0 * r, o1 * r, o2 * r, o3 * r);
        hout4[n * 16 + k * 2 + 1] = make_float4(o4 * r, o5 * r, o6 * r, o7 * r);
    }
}

// ---------------- launch ----------------
extern "C" void kernel_launch(void* const* d_in, const int* in_sizes, int n_in,
                              void* d_out, int out_size) {
    const float* x    = (const float*)d_in[0];   // [40000,128]
    const float* w    = (const float*)d_in[1];   // [128,64]
    const float* bias = (const float*)d_in[2];   // [64]
    const int*   ei   = (const int*)d_in[3];     // [2,640000]
    const int*   src  = ei;
    const int*   dst  = ei + N_EDGES;
    float4*      out4 = (float4*)d_out;          // [40000,64] floats = [40000*16] float4

    // GEMM + fused edge histogram (g_deg zero by invariant)
    gemm_norm_kernel<<<N_NODES / 64, 256>>>(x, w, bias, src);

    scan_onepass_kernel<<<N_PART, SCAN_BLK>>>();   // also re-zeros g_deg
    scatter_kernel<<<(N_EDGES + 255) / 256, 256>>>(src, dst);  // also resets scan state

    // one warp per node: 40000 warps -> 5000 blocks of 256 threads
    int attn_blocks = (N_NODES * 32 + 255) / 256;
    attn_kernel<<<attn_blocks, 256>>>(0, out4);
    attn_kernel<<<attn_blocks, 256>>>(1, out4);
    attn_kernel<<<attn_blocks, 256>>>(2, out4);
}